// round 12
// baseline (speedup 1.0000x reference)
#include <cuda_runtime.h>
#include <cuda_fp16.h>

#define NB_ 16384
#define SCALE_ 0.17677669529663687f  // 1/sqrt(32)

typedef unsigned u32;

// ---- interleaved weight fragment buffers: uint4 = {b0_hi, b1_hi, b0_lo, b1_lo} ----
__device__ __align__(16) uint4 g_wqkv_i[48 * 8 * 32];  // 196608 B
__device__ __align__(16) uint4 g_wo_i[16 * 8 * 32];    //  65536 B

__device__ __forceinline__ void split_pair(float a, float b, u32& hi, u32& lo) {
    __half ha = __float2half_rn(a), hb = __float2half_rn(b);
    __half2 h2 = __halves2half2(ha, hb);
    hi = *(u32*)&h2;
    __half2 l2 = __floats2half2_rn(a - __half2float(ha), b - __half2float(hb));
    lo = *(u32*)&l2;
}
__device__ __forceinline__ u32 pack_hi(float a, float b) {
    __half2 h2 = __floats2half2_rn(a, b);
    return *(u32*)&h2;
}
__device__ __forceinline__ u32 smem_u32(const void* p) {
    u32 a;
    asm("{ .reg .u64 t; cvta.to.shared.u64 t, %1; cvt.u32.u64 %0, t; }" : "=r"(a) : "l"(p));
    return a;
}

__device__ __forceinline__ void mma16816(float* d, const u32* a, const u32* b) {
    asm volatile(
        "mma.sync.aligned.m16n8k16.row.col.f32.f16.f16.f32 "
        "{%0,%1,%2,%3}, {%4,%5,%6,%7}, {%8,%9}, {%0,%1,%2,%3};\n"
        : "+f"(d[0]), "+f"(d[1]), "+f"(d[2]), "+f"(d[3])
        : "r"(a[0]), "r"(a[1]), "r"(a[2]), "r"(a[3]), "r"(b[0]), "r"(b[1]));
}
__device__ __forceinline__ void mma16816_b(float* d, const u32* a, u32 b0, u32 b1) {
    u32 b[2] = {b0, b1};
    mma16816(d, a, b);
}

// ldmatrix x4: four m8n8 b16 tiles in one op.
__device__ __forceinline__ void ldsmA(u32* fr, u32 addr) {
    asm volatile("ldmatrix.sync.aligned.m8n8.x4.shared.b16 {%0,%1,%2,%3}, [%4];"
        : "=r"(fr[0]), "=r"(fr[1]), "=r"(fr[2]), "=r"(fr[3]) : "r"(addr));
}

// ---- prep kernel (verified): 16384 jobs, one uint4 each ----
__global__ void prep_weights(const float* __restrict__ wq, const float* __restrict__ wk,
                             const float* __restrict__ wv, const float* __restrict__ wo) {
    int i = blockIdx.x * blockDim.x + threadIdx.x;
    if (i < 12288) {  // qkv: i = (j*8+kt)*32 + lane
        int lane = i & 31, kt = (i >> 5) & 7, j = i >> 8;
        int tig = lane & 3, gg = lane >> 2;
        int m = j >> 4, h = (j >> 2) & 3, dt = j & 3;
        const float* w = ((m == 0) ? wq : ((m == 1) ? wk : wv)) + h * 4096;
        int d = dt * 8 + gg;
        int e0 = kt * 16 + 2 * tig;
        u32 h0, l0, h1, l1;
        split_pair(w[e0 * 32 + d], w[(e0 + 1) * 32 + d], h0, l0);
        split_pair(w[(e0 + 8) * 32 + d], w[(e0 + 9) * 32 + d], h1, l1);
        g_wqkv_i[i] = make_uint4(h0, h1, l0, l1);
    } else if (i < 16384) {  // wo
        int k = i - 12288;
        int lane = k & 31, kt = (k >> 5) & 7, nt = k >> 8;
        int tig = lane & 3, gg = lane >> 2;
        int o = nt * 8 + gg;
        int hd0 = kt * 16 + 2 * tig;
        u32 h0, l0, h1, l1;
        split_pair(wo[hd0 * 128 + o], wo[(hd0 + 1) * 128 + o], h0, l0);
        split_pair(wo[(hd0 + 8) * 128 + o], wo[(hd0 + 9) * 128 + o], h1, l1);
        g_wo_i[k] = make_uint4(h0, h1, l0, l1);
    }
}

// ---- smem layout (bytes): two X/HD regions + shared QKV ----
// X(bb) hi at bb*17408, lo at +8704. HD(bb) reuses X(bb) (fp16-hi only).
#define XREG(bb) ((bb) * 17408)
#define OFF_QH 34816
#define OFF_QL 45056
#define OFF_KH 55296
#define OFF_KL 65536
#define OFF_VTH 75776
#define SMEM_BYTES 86016

extern __shared__ char smem_raw[];

// ---- phase 1: QKV = X[32,128] @ Wqkv[128,384] (Q/K 3-MMA, V 2-MMA; strided j = nj*8+w) ----
__device__ __forceinline__ void phase1(int w, int g, int tig, int lane, int lrow, int lcol,
                                       u32 sb, u32 xoff, const uint4* wpf, char* smem) {
    __half* QH = (__half*)(smem + OFF_QH);
    __half* QL = (__half*)(smem + OFF_QL);
    __half* KH = (__half*)(smem + OFF_KH);
    __half* KL = (__half*)(smem + OFF_KL);
    __half* VTH = (__half*)(smem + OFF_VTH);

    float acc[2][6][4];
#pragma unroll
    for (int mt = 0; mt < 2; mt++)
#pragma unroll
        for (int nj = 0; nj < 6; nj++)
#pragma unroll
            for (int c = 0; c < 4; c++) acc[mt][nj][c] = 0.0f;

#pragma unroll
    for (int kt = 0; kt < 8; kt++) {
        u32 ah[2][4], al[2][4];
#pragma unroll
        for (int mt = 0; mt < 2; mt++) {
            u32 a0 = sb + xoff + ((mt * 16 + lrow) * 136 + kt * 16 + lcol) * 2;
            ldsmA(ah[mt], a0);
            ldsmA(al[mt], a0 + 8704);
        }
#pragma unroll
        for (int nj = 0; nj < 6; nj++) {
            uint4 bq = (kt == 0) ? wpf[nj]
                                 : __ldg(g_wqkv_i + ((nj * 8 + w) * 8 + kt) * 32 + lane);
            u32 bh[2] = {bq.x, bq.y}, bl[2] = {bq.z, bq.w};
#pragma unroll
            for (int mt = 0; mt < 2; mt++) {
                mma16816(acc[mt][nj], ah[mt], bh);
                mma16816(acc[mt][nj], ah[mt], bl);
                if (nj < 4) mma16816(acc[mt][nj], al[mt], bh);
            }
        }
    }
    // epilogue: split + scatter to Q/K/VT
#pragma unroll
    for (int nj = 0; nj < 6; nj++) {
        int j = nj * 8 + w;
        int h = (j >> 2) & 3, dt = j & 3;
#pragma unroll
        for (int mt = 0; mt < 2; mt++) {
            float c0 = acc[mt][nj][0], c1 = acc[mt][nj][1];
            float c2 = acc[mt][nj][2], c3 = acc[mt][nj][3];
            int r0 = mt * 16 + g, r1 = r0 + 8;
            int d0 = dt * 8 + 2 * tig;
            if (nj < 2) {  // Q
                c0 *= SCALE_; c1 *= SCALE_; c2 *= SCALE_; c3 *= SCALE_;
                u32 hi, lo;
                split_pair(c0, c1, hi, lo);
                *(u32*)&QH[h * 1280 + r0 * 40 + d0] = hi;
                *(u32*)&QL[h * 1280 + r0 * 40 + d0] = lo;
                split_pair(c2, c3, hi, lo);
                *(u32*)&QH[h * 1280 + r1 * 40 + d0] = hi;
                *(u32*)&QL[h * 1280 + r1 * 40 + d0] = lo;
            } else if (nj < 4) {  // K
                u32 hi, lo;
                split_pair(c0, c1, hi, lo);
                *(u32*)&KH[h * 1280 + r0 * 40 + d0] = hi;
                *(u32*)&KL[h * 1280 + r0 * 40 + d0] = lo;
                split_pair(c2, c3, hi, lo);
                *(u32*)&KH[h * 1280 + r1 * 40 + d0] = hi;
                *(u32*)&KL[h * 1280 + r1 * 40 + d0] = lo;
            } else {  // V (fp16-hi only), transposed: VT[h][d][t]
                VTH[h * 1280 + d0 * 40 + r0]       = __float2half_rn(c0);
                VTH[h * 1280 + (d0 + 1) * 40 + r0] = __float2half_rn(c1);
                VTH[h * 1280 + d0 * 40 + r1]       = __float2half_rn(c2);
                VTH[h * 1280 + (d0 + 1) * 40 + r1] = __float2half_rn(c3);
            }
        }
    }
}

// ---- fused phases 2+3+4: scores -> softmax (regs) -> Hd; writes HD(hi) into xoff ----
__device__ __forceinline__ void phase24(int w, int g, int tig, int lrow, int lcol,
                                        u32 sb, u32 xoff, char* smem) {
    __half* HDH = (__half*)(smem + xoff);
    int h = w >> 1, mt = w & 1;
    float acc[4][4];
#pragma unroll
    for (int nt = 0; nt < 4; nt++)
#pragma unroll
        for (int c = 0; c < 4; c++) acc[nt][c] = 0.0f;

    // phase 2: scores = Q @ K^T (3-MMA)
#pragma unroll
    for (int kt = 0; kt < 2; kt++) {
        u32 qh[4], ql[4];
        u32 a0 = sb + OFF_QH + (h * 1280 + (mt * 16 + lrow) * 40 + kt * 16 + lcol) * 2;
        ldsmA(qh, a0);
        ldsmA(ql, a0 + (OFF_QL - OFF_QH));
#pragma unroll
        for (int ntp = 0; ntp < 2; ntp++) {
            u32 kb[4], kl[4];
            u32 ka = sb + OFF_KH + (h * 1280 + (ntp * 16 + lrow) * 40 + kt * 16 + lcol) * 2;
            ldsmA(kb, ka);
            ldsmA(kl, ka + (OFF_KL - OFF_KH));
            mma16816_b(acc[2 * ntp], qh, kb[0], kb[2]);
            mma16816_b(acc[2 * ntp], qh, kl[0], kl[2]);
            mma16816_b(acc[2 * ntp], ql, kb[0], kb[2]);
            mma16816_b(acc[2 * ntp + 1], qh, kb[1], kb[3]);
            mma16816_b(acc[2 * ntp + 1], qh, kl[1], kl[3]);
            mma16816_b(acc[2 * ntp + 1], ql, kb[1], kb[3]);
        }
    }

    // phase 3: softmax in registers (quad shuffle reduction)
    float mx0 = -1e30f, mx1 = -1e30f;
#pragma unroll
    for (int nt = 0; nt < 4; nt++) {
        mx0 = fmaxf(mx0, fmaxf(acc[nt][0], acc[nt][1]));
        mx1 = fmaxf(mx1, fmaxf(acc[nt][2], acc[nt][3]));
    }
    mx0 = fmaxf(mx0, __shfl_xor_sync(0xFFFFFFFF, mx0, 1));
    mx0 = fmaxf(mx0, __shfl_xor_sync(0xFFFFFFFF, mx0, 2));
    mx1 = fmaxf(mx1, __shfl_xor_sync(0xFFFFFFFF, mx1, 1));
    mx1 = fmaxf(mx1, __shfl_xor_sync(0xFFFFFFFF, mx1, 2));
    float s0 = 0.0f, s1 = 0.0f;
#pragma unroll
    for (int nt = 0; nt < 4; nt++) {
        acc[nt][0] = __expf(acc[nt][0] - mx0); s0 += acc[nt][0];
        acc[nt][1] = __expf(acc[nt][1] - mx0); s0 += acc[nt][1];
        acc[nt][2] = __expf(acc[nt][2] - mx1); s1 += acc[nt][2];
        acc[nt][3] = __expf(acc[nt][3] - mx1); s1 += acc[nt][3];
    }
    s0 += __shfl_xor_sync(0xFFFFFFFF, s0, 1);
    s0 += __shfl_xor_sync(0xFFFFFFFF, s0, 2);
    s1 += __shfl_xor_sync(0xFFFFFFFF, s1, 1);
    s1 += __shfl_xor_sync(0xFFFFFFFF, s1, 2);
    float i0 = 1.0f / s0, i1 = 1.0f / s1;

    u32 aah[2][4];
#pragma unroll
    for (int kt = 0; kt < 2; kt++) {
        aah[kt][0] = pack_hi(acc[2 * kt][0] * i0,     acc[2 * kt][1] * i0);
        aah[kt][1] = pack_hi(acc[2 * kt][2] * i1,     acc[2 * kt][3] * i1);
        aah[kt][2] = pack_hi(acc[2 * kt + 1][0] * i0, acc[2 * kt + 1][1] * i0);
        aah[kt][3] = pack_hi(acc[2 * kt + 1][2] * i1, acc[2 * kt + 1][3] * i1);
    }

    // phase 4: Hd = A @ V (A-hi x V-hi)
    float hd[4][4];
#pragma unroll
    for (int nt = 0; nt < 4; nt++)
#pragma unroll
        for (int c = 0; c < 4; c++) hd[nt][c] = 0.0f;
#pragma unroll
    for (int kt = 0; kt < 2; kt++) {
#pragma unroll
        for (int ntp = 0; ntp < 2; ntp++) {
            u32 vb[4];
            u32 va = sb + OFF_VTH + (h * 1280 + (ntp * 16 + lrow) * 40 + kt * 16 + lcol) * 2;
            ldsmA(vb, va);
            mma16816_b(hd[2 * ntp], aah[kt], vb[0], vb[2]);
            mma16816_b(hd[2 * ntp + 1], aah[kt], vb[1], vb[3]);
        }
    }
#pragma unroll
    for (int nt = 0; nt < 4; nt++) {
        int col = h * 32 + nt * 8 + 2 * tig;
        int r0 = mt * 16 + g, r1 = r0 + 8;
        *(u32*)&HDH[r0 * 136 + col] = pack_hi(hd[nt][0], hd[nt][1]);
        *(u32*)&HDH[r1 * 136 + col] = pack_hi(hd[nt][2], hd[nt][3]);
    }
}

// ---- phase 5: out = Hd[32,128] @ WoFlat (Hd-hi x Wo-hi) ----
__device__ __forceinline__ void phase5(int w, int g, int tig, int lane, int lrow, int lcol,
                                       u32 sb, u32 xoff, const uint4* wo_pf, float* ob) {
    float acc[2][2][4];
#pragma unroll
    for (int mt = 0; mt < 2; mt++)
#pragma unroll
        for (int n = 0; n < 2; n++)
#pragma unroll
            for (int c = 0; c < 4; c++) acc[mt][n][c] = 0.0f;
#pragma unroll
    for (int kt = 0; kt < 8; kt++) {
        u32 ah[2][4];
#pragma unroll
        for (int mt = 0; mt < 2; mt++) {
            u32 a0 = sb + xoff + ((mt * 16 + lrow) * 136 + kt * 16 + lcol) * 2;
            ldsmA(ah[mt], a0);
        }
#pragma unroll
        for (int ntl = 0; ntl < 2; ntl++) {
            int nt = w * 2 + ntl;
            uint4 bq = (kt < 2) ? wo_pf[kt * 2 + ntl]
                                : __ldg(g_wo_i + (nt * 8 + kt) * 32 + lane);
            u32 bh[2] = {bq.x, bq.y};
#pragma unroll
            for (int mt = 0; mt < 2; mt++)
                mma16816(acc[mt][ntl], ah[mt], bh);
        }
    }
#pragma unroll
    for (int mt = 0; mt < 2; mt++)
#pragma unroll
        for (int ntl = 0; ntl < 2; ntl++) {
            int nt = w * 2 + ntl;
            int r0 = mt * 16 + g, c = nt * 8 + 2 * tig;
            *(float2*)&ob[r0 * 128 + c] = make_float2(acc[mt][ntl][0], acc[mt][ntl][1]);
            *(float2*)&ob[(r0 + 8) * 128 + c] = make_float2(acc[mt][ntl][2], acc[mt][ntl][3]);
        }
}

__global__ __launch_bounds__(256, 2)
void attn_mma_kernel(const float* __restrict__ x, float* __restrict__ out) {
    const int tid = threadIdx.x;
    const int lane = tid & 31, w = tid >> 5;
    const int g = lane >> 2, tig = lane & 3;
    const long long b0 = (long long)blockIdx.x * 2;
    const u32 sb = smem_u32(smem_raw);

    const int q4 = lane >> 3;
    const int lrow = (lane & 7) + ((q4 & 1) << 3);
    const int lcol = (q4 & 2) << 2;

    // ---- prefetch ph1(b0) kt=0 weight fragments (overlaps x DRAM latency) ----
    uint4 wpf0[6];
#pragma unroll
    for (int nj = 0; nj < 6; nj++)
        wpf0[nj] = __ldg(g_wqkv_i + ((nj * 8 + w) * 8 + 0) * 32 + lane);

    // ---- load x for BOTH batches (contiguous), split fp16 hi/lo ----
    const float2* xb2 = (const float2*)(x + b0 * 4096LL);
#pragma unroll
    for (int i = 0; i < 16; i++) {
        int idx = tid + i * 256;      // 0..4095 float2 across both batches
        int bb = idx >> 11;           // 2048 float2 per batch
        int r = idx & 2047;
        int s = r >> 6, e2 = r & 63;
        float2 v = xb2[idx];
        u32 hi, lo;
        split_pair(v.x, v.y, hi, lo);
        __half* XH = (__half*)(smem_raw + XREG(bb));
        *(u32*)&XH[s * 136 + e2 * 2] = hi;
        *(u32*)&XH[8704 / 2 + s * 136 + e2 * 2] = lo;
    }
    __syncthreads();                                   // S1

    phase1(w, g, tig, lane, lrow, lcol, sb, XREG(0), wpf0, smem_raw);
    __syncthreads();                                   // S2

    // wo_pf for b0's ph5 (hidden under ph2-4)
    uint4 wo_pf[4];
#pragma unroll
    for (int i = 0; i < 4; i++)
        wo_pf[i] = __ldg(g_wo_i + ((w * 2 + (i & 1)) * 8 + (i >> 1)) * 32 + lane);

    phase24(w, g, tig, lrow, lcol, sb, XREG(0), smem_raw);
    __syncthreads();                                   // S3

    // merged segment: ph5(b0) + ph1(b1), no barrier between (independent regions)
    {
        uint4 wpf1[6];
#pragma unroll
        for (int nj = 0; nj < 6; nj++)
            wpf1[nj] = __ldg(g_wqkv_i + ((nj * 8 + w) * 8 + 0) * 32 + lane);

        phase5(w, g, tig, lane, lrow, lcol, sb, XREG(0), wo_pf, out + b0 * 4096LL);
        phase1(w, g, tig, lane, lrow, lcol, sb, XREG(1), wpf1, smem_raw);
    }
    __syncthreads();                                   // S4

#pragma unroll
    for (int i = 0; i < 4; i++)
        wo_pf[i] = __ldg(g_wo_i + ((w * 2 + (i & 1)) * 8 + (i >> 1)) * 32 + lane);

    phase24(w, g, tig, lrow, lcol, sb, XREG(1), smem_raw);
    __syncthreads();                                   // S5

    phase5(w, g, tig, lane, lrow, lcol, sb, XREG(1), wo_pf, out + (b0 + 1) * 4096LL);
}

extern "C" void kernel_launch(void* const* d_in, const int* in_sizes, int n_in,
                              void* d_out, int out_size) {
    const float* x  = (const float*)d_in[0];
    const float* wq = (const float*)d_in[1];
    const float* wk = (const float*)d_in[2];
    const float* wv = (const float*)d_in[3];
    const float* wo = (const float*)d_in[4];
    float* out = (float*)d_out;

    cudaFuncSetAttribute(attn_mma_kernel,
                         cudaFuncAttributeMaxDynamicSharedMemorySize, SMEM_BYTES);

    prep_weights<<<64, 256>>>(wq, wk, wv, wo);
    attn_mma_kernel<<<NB_ / 2, 256, SMEM_BYTES>>>(x, out);
}

// round 13
// speedup vs baseline: 1.0404x; 1.0404x over previous
#include <cuda_runtime.h>
#include <cuda_fp16.h>

#define NB_ 16384
#define SCALE_ 0.17677669529663687f  // 1/sqrt(32)

typedef unsigned u32;

// ---- interleaved weight fragment buffers: uint4 = {b0_hi, b1_hi, b0_lo, b1_lo} ----
__device__ __align__(16) uint4 g_wqkv_i[48 * 8 * 32];  // 196608 B
__device__ __align__(16) uint4 g_wo_i[16 * 8 * 32];    //  65536 B

__device__ __forceinline__ void split_pair(float a, float b, u32& hi, u32& lo) {
    __half ha = __float2half_rn(a), hb = __float2half_rn(b);
    __half2 h2 = __halves2half2(ha, hb);
    hi = *(u32*)&h2;
    __half2 l2 = __floats2half2_rn(a - __half2float(ha), b - __half2float(hb));
    lo = *(u32*)&l2;
}
__device__ __forceinline__ u32 pack_hi(float a, float b) {
    __half2 h2 = __floats2half2_rn(a, b);
    return *(u32*)&h2;
}
__device__ __forceinline__ u32 smem_u32(const void* p) {
    u32 a;
    asm("{ .reg .u64 t; cvta.to.shared.u64 t, %1; cvt.u32.u64 %0, t; }" : "=r"(a) : "l"(p));
    return a;
}

__device__ __forceinline__ void mma16816(float* d, const u32* a, const u32* b) {
    asm volatile(
        "mma.sync.aligned.m16n8k16.row.col.f32.f16.f16.f32 "
        "{%0,%1,%2,%3}, {%4,%5,%6,%7}, {%8,%9}, {%0,%1,%2,%3};\n"
        : "+f"(d[0]), "+f"(d[1]), "+f"(d[2]), "+f"(d[3])
        : "r"(a[0]), "r"(a[1]), "r"(a[2]), "r"(a[3]), "r"(b[0]), "r"(b[1]));
}
__device__ __forceinline__ void mma16816_b(float* d, const u32* a, u32 b0, u32 b1) {
    u32 b[2] = {b0, b1};
    mma16816(d, a, b);
}

// ldmatrix x4: four m8n8 b16 tiles in one op.
__device__ __forceinline__ void ldsmA(u32* fr, u32 addr) {
    asm volatile("ldmatrix.sync.aligned.m8n8.x4.shared.b16 {%0,%1,%2,%3}, [%4];"
        : "=r"(fr[0]), "=r"(fr[1]), "=r"(fr[2]), "=r"(fr[3]) : "r"(addr));
}

// ---- prep kernel (verified): 16384 jobs, one uint4 each ----
__global__ void prep_weights(const float* __restrict__ wq, const float* __restrict__ wk,
                             const float* __restrict__ wv, const float* __restrict__ wo) {
    int i = blockIdx.x * blockDim.x + threadIdx.x;
    if (i < 12288) {  // qkv: i = (j*8+kt)*32 + lane
        int lane = i & 31, kt = (i >> 5) & 7, j = i >> 8;
        int tig = lane & 3, gg = lane >> 2;
        int m = j >> 4, h = (j >> 2) & 3, dt = j & 3;
        const float* w = ((m == 0) ? wq : ((m == 1) ? wk : wv)) + h * 4096;
        int d = dt * 8 + gg;
        int e0 = kt * 16 + 2 * tig;
        u32 h0, l0, h1, l1;
        split_pair(w[e0 * 32 + d], w[(e0 + 1) * 32 + d], h0, l0);
        split_pair(w[(e0 + 8) * 32 + d], w[(e0 + 9) * 32 + d], h1, l1);
        g_wqkv_i[i] = make_uint4(h0, h1, l0, l1);
    } else if (i < 16384) {  // wo
        int k = i - 12288;
        int lane = k & 31, kt = (k >> 5) & 7, nt = k >> 8;
        int tig = lane & 3, gg = lane >> 2;
        int o = nt * 8 + gg;
        int hd0 = kt * 16 + 2 * tig;
        u32 h0, l0, h1, l1;
        split_pair(wo[hd0 * 128 + o], wo[(hd0 + 1) * 128 + o], h0, l0);
        split_pair(wo[(hd0 + 8) * 128 + o], wo[(hd0 + 9) * 128 + o], h1, l1);
        g_wo_i[k] = make_uint4(h0, h1, l0, l1);
    }
}

// ---- smem layout (bytes); Q buffers ELIMINATED (Q lives in registers) ----
#define OFF_XH 0
#define OFF_XL 8704
#define OFF_KH 17408
#define OFF_KL 27648
#define OFF_VTH 37888
#define SMEM_BYTES 48128

extern __shared__ char smem_raw[];

__global__ __launch_bounds__(256, 2)
void attn_mma_kernel(const float* __restrict__ x, float* __restrict__ out) {
    __half* XH = (__half*)(smem_raw + OFF_XH);
    __half* XL = (__half*)(smem_raw + OFF_XL);
    __half* KH = (__half*)(smem_raw + OFF_KH);
    __half* KL = (__half*)(smem_raw + OFF_KL);
    __half* VTH = (__half*)(smem_raw + OFF_VTH);
    __half* HDH = XH;  // reuse after phase 1 (fp16-hi only)

    const int tid = threadIdx.x;
    const int lane = tid & 31, w = tid >> 5;
    const int g = lane >> 2, tig = lane & 3;
    const long long b = blockIdx.x;
    const u32 sb = smem_u32(smem_raw);

    // ldmatrix per-lane address offsets
    const int q4 = lane >> 3;
    const int lrow = (lane & 7) + ((q4 & 1) << 3);
    const int lcol = (q4 & 2) << 2;  // 0 or 8 halfs

    // warp identity for Q ownership / ph2-4
    const int hq = w >> 1, mtq = w & 1;

    // ---- prefetch ph1 kt=0 weight fragments ----
    // Q: j = hq*4+dt (4); K: j = 16+2w+jj (2); V: j = 32+2w+jj (2)
    uint4 wpfQ[4], wpfK[2], wpfV[2];
#pragma unroll
    for (int dt = 0; dt < 4; dt++)
        wpfQ[dt] = __ldg(g_wqkv_i + ((hq * 4 + dt) * 8 + 0) * 32 + lane);
#pragma unroll
    for (int jj = 0; jj < 2; jj++) {
        wpfK[jj] = __ldg(g_wqkv_i + ((16 + 2 * w + jj) * 8 + 0) * 32 + lane);
        wpfV[jj] = __ldg(g_wqkv_i + ((32 + 2 * w + jj) * 8 + 0) * 32 + lane);
    }

    // ---- load x, split fp16 hi/lo ----
    const float2* xb2 = (const float2*)(x + b * 4096LL);
#pragma unroll
    for (int i = 0; i < 8; i++) {
        int idx = tid + i * 256;  // s = idx/64, e2 = idx%64
        int s = idx >> 6, e2 = idx & 63;
        float2 v = xb2[idx];
        u32 hi, lo;
        split_pair(v.x, v.y, hi, lo);
        *(u32*)&XH[s * 136 + e2 * 2] = hi;
        *(u32*)&XL[s * 136 + e2 * 2] = lo;
    }
    __syncthreads();

    // Q fragments held in registers through ph2 (D-layout == A-layout)
    u32 QHf[2][4], QLf[2][4];

    // ---- phase 1: QKV = X[32,128] @ Wqkv[128,384] ----
    // Q: warp computes OWN (hq, mtq) tiles, dt 0..3 -> stays in registers.
    // K: 2 j-cols x 2 mt (3-MMA). V: 2 j-cols x 2 mt (2-MMA), transposed store.
    {
        float accq[4][4], acck[2][2][4], accv[2][2][4];
#pragma unroll
        for (int t = 0; t < 4; t++)
#pragma unroll
            for (int c = 0; c < 4; c++) accq[t][c] = 0.0f;
#pragma unroll
        for (int jj = 0; jj < 2; jj++)
#pragma unroll
            for (int mt = 0; mt < 2; mt++)
#pragma unroll
                for (int c = 0; c < 4; c++) { acck[jj][mt][c] = 0.0f; accv[jj][mt][c] = 0.0f; }

#pragma unroll
        for (int kt = 0; kt < 8; kt++) {
            u32 ah[2][4], al[2][4];
#pragma unroll
            for (int mt = 0; mt < 2; mt++) {
                u32 a0 = sb + OFF_XH + ((mt * 16 + lrow) * 136 + kt * 16 + lcol) * 2;
                ldsmA(ah[mt], a0);
                ldsmA(al[mt], a0 + (OFF_XL - OFF_XH));
            }
            // Q (own mt only, 3-MMA)
#pragma unroll
            for (int dt = 0; dt < 4; dt++) {
                uint4 bq = (kt == 0) ? wpfQ[dt]
                                     : __ldg(g_wqkv_i + ((hq * 4 + dt) * 8 + kt) * 32 + lane);
                u32 bh[2] = {bq.x, bq.y}, bl[2] = {bq.z, bq.w};
                mma16816(accq[dt], ah[mtq], bh);
                mma16816(accq[dt], ah[mtq], bl);
                mma16816(accq[dt], al[mtq], bh);
            }
            // K (both mt, 3-MMA)
#pragma unroll
            for (int jj = 0; jj < 2; jj++) {
                uint4 bq = (kt == 0) ? wpfK[jj]
                                     : __ldg(g_wqkv_i + ((16 + 2 * w + jj) * 8 + kt) * 32 + lane);
                u32 bh[2] = {bq.x, bq.y}, bl[2] = {bq.z, bq.w};
#pragma unroll
                for (int mt = 0; mt < 2; mt++) {
                    mma16816(acck[jj][mt], ah[mt], bh);
                    mma16816(acck[jj][mt], ah[mt], bl);
                    mma16816(acck[jj][mt], al[mt], bh);
                }
            }
            // V (both mt, 2-MMA)
#pragma unroll
            for (int jj = 0; jj < 2; jj++) {
                uint4 bq = (kt == 0) ? wpfV[jj]
                                     : __ldg(g_wqkv_i + ((32 + 2 * w + jj) * 8 + kt) * 32 + lane);
                u32 bh[2] = {bq.x, bq.y}, bl[2] = {bq.z, bq.w};
#pragma unroll
                for (int mt = 0; mt < 2; mt++) {
                    mma16816(accv[jj][mt], ah[mt], bh);
                    mma16816(accv[jj][mt], ah[mt], bl);
                }
            }
        }

        // ---- Q epilogue: scale + split DIRECTLY into A-fragment registers ----
        // a-frag(kt): {dt=2kt:(c0,c1), dt=2kt:(c2,c3), dt=2kt+1:(c0,c1), dt=2kt+1:(c2,c3)}
#pragma unroll
        for (int kt = 0; kt < 2; kt++) {
            split_pair(accq[2 * kt][0] * SCALE_, accq[2 * kt][1] * SCALE_, QHf[kt][0], QLf[kt][0]);
            split_pair(accq[2 * kt][2] * SCALE_, accq[2 * kt][3] * SCALE_, QHf[kt][1], QLf[kt][1]);
            split_pair(accq[2 * kt + 1][0] * SCALE_, accq[2 * kt + 1][1] * SCALE_, QHf[kt][2], QLf[kt][2]);
            split_pair(accq[2 * kt + 1][2] * SCALE_, accq[2 * kt + 1][3] * SCALE_, QHf[kt][3], QLf[kt][3]);
        }

        // ---- K/V epilogue: split + scatter to smem ----
#pragma unroll
        for (int jj = 0; jj < 2; jj++) {
            int j = 2 * w + jj;
            int h = j >> 2, dt = j & 3;
#pragma unroll
            for (int mt = 0; mt < 2; mt++) {
                int r0 = mt * 16 + g, r1 = r0 + 8;
                int d0 = dt * 8 + 2 * tig;
                {  // K
                    u32 hi, lo;
                    split_pair(acck[jj][mt][0], acck[jj][mt][1], hi, lo);
                    *(u32*)&KH[h * 1280 + r0 * 40 + d0] = hi;
                    *(u32*)&KL[h * 1280 + r0 * 40 + d0] = lo;
                    split_pair(acck[jj][mt][2], acck[jj][mt][3], hi, lo);
                    *(u32*)&KH[h * 1280 + r1 * 40 + d0] = hi;
                    *(u32*)&KL[h * 1280 + r1 * 40 + d0] = lo;
                }
                {  // V (fp16-hi only), transposed: VT[h][d][t]
                    VTH[h * 1280 + d0 * 40 + r0]       = __float2half_rn(accv[jj][mt][0]);
                    VTH[h * 1280 + (d0 + 1) * 40 + r0] = __float2half_rn(accv[jj][mt][1]);
                    VTH[h * 1280 + d0 * 40 + r1]       = __float2half_rn(accv[jj][mt][2]);
                    VTH[h * 1280 + (d0 + 1) * 40 + r1] = __float2half_rn(accv[jj][mt][3]);
                }
            }
        }
    }
    __syncthreads();

    // ---- prefetch ph5 Wo fragments for kt=0,1 ----
    uint4 wo_pf[4];
#pragma unroll
    for (int i = 0; i < 4; i++) {
        int kt = i >> 1, ntl = i & 1;
        wo_pf[i] = __ldg(g_wo_i + ((w * 2 + ntl) * 8 + kt) * 32 + lane);
    }

    // ---- fused phases 2+3+4 (register-resident, warp-local) ----
    {
        float acc[4][4];
#pragma unroll
        for (int nt = 0; nt < 4; nt++)
#pragma unroll
            for (int c = 0; c < 4; c++) acc[nt][c] = 0.0f;

        // phase 2: scores = Q @ K^T (3-MMA; Q from registers, zero smem roundtrip)
#pragma unroll
        for (int kt = 0; kt < 2; kt++) {
#pragma unroll
            for (int ntp = 0; ntp < 2; ntp++) {
                u32 kb[4], kl[4];
                u32 ka = sb + OFF_KH + (hq * 1280 + (ntp * 16 + lrow) * 40 + kt * 16 + lcol) * 2;
                ldsmA(kb, ka);
                ldsmA(kl, ka + (OFF_KL - OFF_KH));
                mma16816_b(acc[2 * ntp], QHf[kt], kb[0], kb[2]);
                mma16816_b(acc[2 * ntp], QHf[kt], kl[0], kl[2]);
                mma16816_b(acc[2 * ntp], QLf[kt], kb[0], kb[2]);
                mma16816_b(acc[2 * ntp + 1], QHf[kt], kb[1], kb[3]);
                mma16816_b(acc[2 * ntp + 1], QHf[kt], kl[1], kl[3]);
                mma16816_b(acc[2 * ntp + 1], QLf[kt], kb[1], kb[3]);
            }
        }

        // phase 3: softmax in registers (quad shuffle reduction)
        float mx0 = -1e30f, mx1 = -1e30f;
#pragma unroll
        for (int nt = 0; nt < 4; nt++) {
            mx0 = fmaxf(mx0, fmaxf(acc[nt][0], acc[nt][1]));
            mx1 = fmaxf(mx1, fmaxf(acc[nt][2], acc[nt][3]));
        }
        mx0 = fmaxf(mx0, __shfl_xor_sync(0xFFFFFFFF, mx0, 1));
        mx0 = fmaxf(mx0, __shfl_xor_sync(0xFFFFFFFF, mx0, 2));
        mx1 = fmaxf(mx1, __shfl_xor_sync(0xFFFFFFFF, mx1, 1));
        mx1 = fmaxf(mx1, __shfl_xor_sync(0xFFFFFFFF, mx1, 2));
        float s0 = 0.0f, s1 = 0.0f;
#pragma unroll
        for (int nt = 0; nt < 4; nt++) {
            acc[nt][0] = __expf(acc[nt][0] - mx0); s0 += acc[nt][0];
            acc[nt][1] = __expf(acc[nt][1] - mx0); s0 += acc[nt][1];
            acc[nt][2] = __expf(acc[nt][2] - mx1); s1 += acc[nt][2];
            acc[nt][3] = __expf(acc[nt][3] - mx1); s1 += acc[nt][3];
        }
        s0 += __shfl_xor_sync(0xFFFFFFFF, s0, 1);
        s0 += __shfl_xor_sync(0xFFFFFFFF, s0, 2);
        s1 += __shfl_xor_sync(0xFFFFFFFF, s1, 1);
        s1 += __shfl_xor_sync(0xFFFFFFFF, s1, 2);
        float i0 = 1.0f / s0, i1 = 1.0f / s1;

        // normalized scores -> A-fragments, fp16-hi only
        u32 aah[2][4];
#pragma unroll
        for (int kt = 0; kt < 2; kt++) {
            aah[kt][0] = pack_hi(acc[2 * kt][0] * i0,     acc[2 * kt][1] * i0);
            aah[kt][1] = pack_hi(acc[2 * kt][2] * i1,     acc[2 * kt][3] * i1);
            aah[kt][2] = pack_hi(acc[2 * kt + 1][0] * i0, acc[2 * kt + 1][1] * i0);
            aah[kt][3] = pack_hi(acc[2 * kt + 1][2] * i1, acc[2 * kt + 1][3] * i1);
        }

        // phase 4: Hd = A @ V (A-hi x V-hi)
        float hd[4][4];
#pragma unroll
        for (int nt = 0; nt < 4; nt++)
#pragma unroll
            for (int c = 0; c < 4; c++) hd[nt][c] = 0.0f;
#pragma unroll
        for (int kt = 0; kt < 2; kt++) {
#pragma unroll
            for (int ntp = 0; ntp < 2; ntp++) {
                u32 vb[4];
                u32 va = sb + OFF_VTH + (hq * 1280 + (ntp * 16 + lrow) * 40 + kt * 16 + lcol) * 2;
                ldsmA(vb, va);
                mma16816_b(hd[2 * ntp], aah[kt], vb[0], vb[2]);
                mma16816_b(hd[2 * ntp + 1], aah[kt], vb[1], vb[3]);
            }
        }
        // epilogue -> HDH only (fp16-hi)
#pragma unroll
        for (int nt = 0; nt < 4; nt++) {
            int col = hq * 32 + nt * 8 + 2 * tig;
            int r0 = mtq * 16 + g, r1 = r0 + 8;
            *(u32*)&HDH[r0 * 136 + col] = pack_hi(hd[nt][0], hd[nt][1]);
            *(u32*)&HDH[r1 * 136 + col] = pack_hi(hd[nt][2], hd[nt][3]);
        }
    }
    __syncthreads();

    // ---- phase 5: out = Hd[32,128] @ WoFlat[128,128]  (Hd-hi x Wo-hi) ----
    {
        float acc[2][2][4];
#pragma unroll
        for (int mt = 0; mt < 2; mt++)
#pragma unroll
            for (int n = 0; n < 2; n++)
#pragma unroll
                for (int c = 0; c < 4; c++) acc[mt][n][c] = 0.0f;
#pragma unroll
        for (int kt = 0; kt < 8; kt++) {
            u32 ah[2][4];
#pragma unroll
            for (int mt = 0; mt < 2; mt++) {
                u32 a0 = sb + OFF_XH + ((mt * 16 + lrow) * 136 + kt * 16 + lcol) * 2;
                ldsmA(ah[mt], a0);
            }
#pragma unroll
            for (int ntl = 0; ntl < 2; ntl++) {
                int nt = w * 2 + ntl;
                uint4 bq = (kt < 2) ? wo_pf[kt * 2 + ntl]
                                    : __ldg(g_wo_i + (nt * 8 + kt) * 32 + lane);
                u32 bh[2] = {bq.x, bq.y};
#pragma unroll
                for (int mt = 0; mt < 2; mt++)
                    mma16816(acc[mt][ntl], ah[mt], bh);
            }
        }
        float* ob = out + b * 4096LL;
#pragma unroll
        for (int mt = 0; mt < 2; mt++)
#pragma unroll
            for (int ntl = 0; ntl < 2; ntl++) {
                int nt = w * 2 + ntl;
                int r0 = mt * 16 + g, c = nt * 8 + 2 * tig;
                *(float2*)&ob[r0 * 128 + c] = make_float2(acc[mt][ntl][0], acc[mt][ntl][1]);
                *(float2*)&ob[(r0 + 8) * 128 + c] = make_float2(acc[mt][ntl][2], acc[mt][ntl][3]);
            }
    }
}

extern "C" void kernel_launch(void* const* d_in, const int* in_sizes, int n_in,
                              void* d_out, int out_size) {
    const float* x  = (const float*)d_in[0];
    const float* wq = (const float*)d_in[1];
    const float* wk = (const float*)d_in[2];
    const float* wv = (const float*)d_in[3];
    const float* wo = (const float*)d_in[4];
    float* out = (float*)d_out;

    cudaFuncSetAttribute(attn_mma_kernel,
                         cudaFuncAttributeMaxDynamicSharedMemorySize, SMEM_BYTES);

    prep_weights<<<64, 256>>>(wq, wk, wv, wo);
    attn_mma_kernel<<<NB_, 256, SMEM_BYTES>>>(x, out);
}

// round 14
// speedup vs baseline: 1.0432x; 1.0027x over previous
#include <cuda_runtime.h>
#include <cuda_fp16.h>

#define NB_ 16384
#define SCALE_ 0.17677669529663687f  // 1/sqrt(32)

typedef unsigned u32;

// ---- interleaved weight fragment buffers: uint4 = {b0_hi, b1_hi, b0_lo, b1_lo} ----
__device__ __align__(16) uint4 g_wqkv_i[48 * 8 * 32];  // 196608 B
__device__ __align__(16) uint4 g_wo_i[16 * 8 * 32];    //  65536 B

__device__ __forceinline__ void split_pair(float a, float b, u32& hi, u32& lo) {
    __half ha = __float2half_rn(a), hb = __float2half_rn(b);
    __half2 h2 = __halves2half2(ha, hb);
    hi = *(u32*)&h2;
    __half2 l2 = __floats2half2_rn(a - __half2float(ha), b - __half2float(hb));
    lo = *(u32*)&l2;
}
__device__ __forceinline__ u32 pack_hi(float a, float b) {
    __half2 h2 = __floats2half2_rn(a, b);
    return *(u32*)&h2;
}
__device__ __forceinline__ u32 smem_u32(const void* p) {
    u32 a;
    asm("{ .reg .u64 t; cvta.to.shared.u64 t, %1; cvt.u32.u64 %0, t; }" : "=r"(a) : "l"(p));
    return a;
}

__device__ __forceinline__ void mma16816(float* d, const u32* a, const u32* b) {
    asm volatile(
        "mma.sync.aligned.m16n8k16.row.col.f32.f16.f16.f32 "
        "{%0,%1,%2,%3}, {%4,%5,%6,%7}, {%8,%9}, {%0,%1,%2,%3};\n"
        : "+f"(d[0]), "+f"(d[1]), "+f"(d[2]), "+f"(d[3])
        : "r"(a[0]), "r"(a[1]), "r"(a[2]), "r"(a[3]), "r"(b[0]), "r"(b[1]));
}
__device__ __forceinline__ void mma16816_b(float* d, const u32* a, u32 b0, u32 b1) {
    u32 b[2] = {b0, b1};
    mma16816(d, a, b);
}

// ldmatrix x4: four m8n8 b16 tiles in one op.
__device__ __forceinline__ void ldsmA(u32* fr, u32 addr) {
    asm volatile("ldmatrix.sync.aligned.m8n8.x4.shared.b16 {%0,%1,%2,%3}, [%4];"
        : "=r"(fr[0]), "=r"(fr[1]), "=r"(fr[2]), "=r"(fr[3]) : "r"(addr));
}
// ldmatrix x4 transposed (for V stored [t][d], delivers V^T B-fragments)
__device__ __forceinline__ void ldsmT(u32* fr, u32 addr) {
    asm volatile("ldmatrix.sync.aligned.m8n8.x4.trans.shared.b16 {%0,%1,%2,%3}, [%4];"
        : "=r"(fr[0]), "=r"(fr[1]), "=r"(fr[2]), "=r"(fr[3]) : "r"(addr));
}

// ---- prep kernel (verified): 16384 jobs, one uint4 each ----
__global__ void prep_weights(const float* __restrict__ wq, const float* __restrict__ wk,
                             const float* __restrict__ wv, const float* __restrict__ wo) {
    int i = blockIdx.x * blockDim.x + threadIdx.x;
    if (i < 12288) {  // qkv: i = (j*8+kt)*32 + lane
        int lane = i & 31, kt = (i >> 5) & 7, j = i >> 8;
        int tig = lane & 3, gg = lane >> 2;
        int m = j >> 4, h = (j >> 2) & 3, dt = j & 3;
        const float* w = ((m == 0) ? wq : ((m == 1) ? wk : wv)) + h * 4096;
        int d = dt * 8 + gg;
        int e0 = kt * 16 + 2 * tig;
        u32 h0, l0, h1, l1;
        split_pair(w[e0 * 32 + d], w[(e0 + 1) * 32 + d], h0, l0);
        split_pair(w[(e0 + 8) * 32 + d], w[(e0 + 9) * 32 + d], h1, l1);
        g_wqkv_i[i] = make_uint4(h0, h1, l0, l1);
    } else if (i < 16384) {  // wo
        int k = i - 12288;
        int lane = k & 31, kt = (k >> 5) & 7, nt = k >> 8;
        int tig = lane & 3, gg = lane >> 2;
        int o = nt * 8 + gg;
        int hd0 = kt * 16 + 2 * tig;
        u32 h0, l0, h1, l1;
        split_pair(wo[hd0 * 128 + o], wo[(hd0 + 1) * 128 + o], h0, l0);
        split_pair(wo[(hd0 + 8) * 128 + o], wo[(hd0 + 9) * 128 + o], h1, l1);
        g_wo_i[k] = make_uint4(h0, h1, l0, l1);
    }
}

// ---- smem layout (bytes); V stored [t][d] hi-only ----
#define OFF_XH 0
#define OFF_XL 8704
#define OFF_QH 17408
#define OFF_QL 27648
#define OFF_KH 37888
#define OFF_KL 48128
#define OFF_VH 58368
#define SMEM_BYTES 68608

extern __shared__ char smem_raw[];

__global__ __launch_bounds__(256, 2)
void attn_mma_kernel(const float* __restrict__ x, float* __restrict__ out) {
    __half* XH = (__half*)(smem_raw + OFF_XH);
    __half* XL = (__half*)(smem_raw + OFF_XL);
    __half* QH = (__half*)(smem_raw + OFF_QH);
    __half* QL = (__half*)(smem_raw + OFF_QL);
    __half* KH = (__half*)(smem_raw + OFF_KH);
    __half* KL = (__half*)(smem_raw + OFF_KL);
    __half* VH = (__half*)(smem_raw + OFF_VH);
    __half* HDH = XH;  // reuse after phase 1 (fp16-hi only)

    const int tid = threadIdx.x;
    const int lane = tid & 31, w = tid >> 5;
    const int g = lane >> 2, tig = lane & 3;
    const long long b = blockIdx.x;
    const u32 sb = smem_u32(smem_raw);

    // ldmatrix per-lane address offsets
    const int q4 = lane >> 3;
    const int lrow = (lane & 7) + ((q4 & 1) << 3);
    const int lcol = (q4 & 2) << 2;  // 0 or 8 halfs
    // trans-ldmatrix offsets (tile row = k/t, tile col = n/d)
    const int vrow = (lane & 7) + ((q4 & 2) << 2);
    const int vcol = (q4 & 1) << 3;

    // ---- prefetch ph1 kt=0 weight fragments (strided j = nj*8 + w) ----
    uint4 wpf[6];
#pragma unroll
    for (int nj = 0; nj < 6; nj++)
        wpf[nj] = __ldg(g_wqkv_i + ((nj * 8 + w) * 8 + 0) * 32 + lane);

    // ---- load x, split fp16 hi/lo ----
    const float2* xb2 = (const float2*)(x + b * 4096LL);
#pragma unroll
    for (int i = 0; i < 8; i++) {
        int idx = tid + i * 256;  // s = idx/64, e2 = idx%64
        int s = idx >> 6, e2 = idx & 63;
        float2 v = xb2[idx];
        u32 hi, lo;
        split_pair(v.x, v.y, hi, lo);
        *(u32*)&XH[s * 136 + e2 * 2] = hi;
        *(u32*)&XL[s * 136 + e2 * 2] = lo;
    }
    __syncthreads();

    // ---- phase 1: QKV = X[32,128] @ Wqkv[128,384] ----
    // j = nj*8 + w; nj 0,1 = Q (3-MMA); 2,3 = K (3-MMA); 4,5 = V (2-MMA).
    {
        float acc[2][6][4];
#pragma unroll
        for (int mt = 0; mt < 2; mt++)
#pragma unroll
            for (int nj = 0; nj < 6; nj++)
#pragma unroll
                for (int c = 0; c < 4; c++) acc[mt][nj][c] = 0.0f;

#pragma unroll
        for (int kt = 0; kt < 8; kt++) {
            u32 ah[2][4], al[2][4];
#pragma unroll
            for (int mt = 0; mt < 2; mt++) {
                u32 a0 = sb + OFF_XH + ((mt * 16 + lrow) * 136 + kt * 16 + lcol) * 2;
                ldsmA(ah[mt], a0);
                ldsmA(al[mt], a0 + (OFF_XL - OFF_XH));
            }
#pragma unroll
            for (int nj = 0; nj < 6; nj++) {
                uint4 bq = (kt == 0) ? wpf[nj]
                                     : __ldg(g_wqkv_i + ((nj * 8 + w) * 8 + kt) * 32 + lane);
                u32 bh[2] = {bq.x, bq.y}, bl[2] = {bq.z, bq.w};
#pragma unroll
                for (int mt = 0; mt < 2; mt++) {
                    mma16816(acc[mt][nj], ah[mt], bh);
                    mma16816(acc[mt][nj], ah[mt], bl);
                    if (nj < 4) mma16816(acc[mt][nj], al[mt], bh);
                }
            }
        }
        // epilogue: split + scatter to Q/K/V
#pragma unroll
        for (int nj = 0; nj < 6; nj++) {
            int j = nj * 8 + w;
            int h = (j >> 2) & 3, dt = j & 3;
#pragma unroll
            for (int mt = 0; mt < 2; mt++) {
                float c0 = acc[mt][nj][0], c1 = acc[mt][nj][1];
                float c2 = acc[mt][nj][2], c3 = acc[mt][nj][3];
                int r0 = mt * 16 + g, r1 = r0 + 8;
                int d0 = dt * 8 + 2 * tig;
                if (nj < 2) {  // Q
                    c0 *= SCALE_; c1 *= SCALE_; c2 *= SCALE_; c3 *= SCALE_;
                    u32 hi, lo;
                    split_pair(c0, c1, hi, lo);
                    *(u32*)&QH[h * 1280 + r0 * 40 + d0] = hi;
                    *(u32*)&QL[h * 1280 + r0 * 40 + d0] = lo;
                    split_pair(c2, c3, hi, lo);
                    *(u32*)&QH[h * 1280 + r1 * 40 + d0] = hi;
                    *(u32*)&QL[h * 1280 + r1 * 40 + d0] = lo;
                } else if (nj < 4) {  // K
                    u32 hi, lo;
                    split_pair(c0, c1, hi, lo);
                    *(u32*)&KH[h * 1280 + r0 * 40 + d0] = hi;
                    *(u32*)&KL[h * 1280 + r0 * 40 + d0] = lo;
                    split_pair(c2, c3, hi, lo);
                    *(u32*)&KH[h * 1280 + r1 * 40 + d0] = hi;
                    *(u32*)&KL[h * 1280 + r1 * 40 + d0] = lo;
                } else {  // V (fp16-hi only), stored [t][d] like K — clean u32 stores
                    *(u32*)&VH[h * 1280 + r0 * 40 + d0] = pack_hi(c0, c1);
                    *(u32*)&VH[h * 1280 + r1 * 40 + d0] = pack_hi(c2, c3);
                }
            }
        }
    }
    __syncthreads();

    // ---- prefetch ph5 Wo fragments for kt=0 (new nt mapping: gw*4+ntl) ----
    uint4 wo_pf[4];
#pragma unroll
    for (int ntl = 0; ntl < 4; ntl++)
        wo_pf[ntl] = __ldg(g_wo_i + (((w >> 1) * 4 + ntl) * 8 + 0) * 32 + lane);

    // ---- fused phases 2+3+4 (register-resident, warp-local) ----
    {
        int h = w >> 1, mt = w & 1;
        float acc[4][4];
#pragma unroll
        for (int nt = 0; nt < 4; nt++)
#pragma unroll
            for (int c = 0; c < 4; c++) acc[nt][c] = 0.0f;

        // phase 2: scores = Q @ K^T (3-MMA)
#pragma unroll
        for (int kt = 0; kt < 2; kt++) {
            u32 qh[4], ql[4];
            u32 a0 = sb + OFF_QH + (h * 1280 + (mt * 16 + lrow) * 40 + kt * 16 + lcol) * 2;
            ldsmA(qh, a0);
            ldsmA(ql, a0 + (OFF_QL - OFF_QH));
#pragma unroll
            for (int ntp = 0; ntp < 2; ntp++) {
                u32 kb[4], kl[4];
                u32 ka = sb + OFF_KH + (h * 1280 + (ntp * 16 + lrow) * 40 + kt * 16 + lcol) * 2;
                ldsmA(kb, ka);
                ldsmA(kl, ka + (OFF_KL - OFF_KH));
                mma16816_b(acc[2 * ntp], qh, kb[0], kb[2]);
                mma16816_b(acc[2 * ntp], qh, kl[0], kl[2]);
                mma16816_b(acc[2 * ntp], ql, kb[0], kb[2]);
                mma16816_b(acc[2 * ntp + 1], qh, kb[1], kb[3]);
                mma16816_b(acc[2 * ntp + 1], qh, kl[1], kl[3]);
                mma16816_b(acc[2 * ntp + 1], ql, kb[1], kb[3]);
            }
        }

        // phase 3: softmax in registers (quad shuffle reduction)
        float mx0 = -1e30f, mx1 = -1e30f;
#pragma unroll
        for (int nt = 0; nt < 4; nt++) {
            mx0 = fmaxf(mx0, fmaxf(acc[nt][0], acc[nt][1]));
            mx1 = fmaxf(mx1, fmaxf(acc[nt][2], acc[nt][3]));
        }
        mx0 = fmaxf(mx0, __shfl_xor_sync(0xFFFFFFFF, mx0, 1));
        mx0 = fmaxf(mx0, __shfl_xor_sync(0xFFFFFFFF, mx0, 2));
        mx1 = fmaxf(mx1, __shfl_xor_sync(0xFFFFFFFF, mx1, 1));
        mx1 = fmaxf(mx1, __shfl_xor_sync(0xFFFFFFFF, mx1, 2));
        float s0 = 0.0f, s1 = 0.0f;
#pragma unroll
        for (int nt = 0; nt < 4; nt++) {
            acc[nt][0] = __expf(acc[nt][0] - mx0); s0 += acc[nt][0];
            acc[nt][1] = __expf(acc[nt][1] - mx0); s0 += acc[nt][1];
            acc[nt][2] = __expf(acc[nt][2] - mx1); s1 += acc[nt][2];
            acc[nt][3] = __expf(acc[nt][3] - mx1); s1 += acc[nt][3];
        }
        s0 += __shfl_xor_sync(0xFFFFFFFF, s0, 1);
        s0 += __shfl_xor_sync(0xFFFFFFFF, s0, 2);
        s1 += __shfl_xor_sync(0xFFFFFFFF, s1, 1);
        s1 += __shfl_xor_sync(0xFFFFFFFF, s1, 2);
        float i0 = 1.0f / s0, i1 = 1.0f / s1;

        // normalized scores -> A-fragments, fp16-hi only
        u32 aah[2][4];
#pragma unroll
        for (int kt = 0; kt < 2; kt++) {
            aah[kt][0] = pack_hi(acc[2 * kt][0] * i0,     acc[2 * kt][1] * i0);
            aah[kt][1] = pack_hi(acc[2 * kt][2] * i1,     acc[2 * kt][3] * i1);
            aah[kt][2] = pack_hi(acc[2 * kt + 1][0] * i0, acc[2 * kt + 1][1] * i0);
            aah[kt][3] = pack_hi(acc[2 * kt + 1][2] * i1, acc[2 * kt + 1][3] * i1);
        }

        // phase 4: Hd = A @ V (A-hi x V-hi); V^T fragments via trans-ldmatrix
        float hd[4][4];
#pragma unroll
        for (int nt = 0; nt < 4; nt++)
#pragma unroll
            for (int c = 0; c < 4; c++) hd[nt][c] = 0.0f;
#pragma unroll
        for (int kt = 0; kt < 2; kt++) {
#pragma unroll
            for (int ntp = 0; ntp < 2; ntp++) {
                u32 vb[4];
                u32 va = sb + OFF_VH + (h * 1280 + (kt * 16 + vrow) * 40 + ntp * 16 + vcol) * 2;
                ldsmT(vb, va);
                mma16816_b(hd[2 * ntp], aah[kt], vb[0], vb[2]);
                mma16816_b(hd[2 * ntp + 1], aah[kt], vb[1], vb[3]);
            }
        }
        // epilogue -> HDH only (fp16-hi)
#pragma unroll
        for (int nt = 0; nt < 4; nt++) {
            int col = h * 32 + nt * 8 + 2 * tig;
            int r0 = mt * 16 + g, r1 = r0 + 8;
            *(u32*)&HDH[r0 * 136 + col] = pack_hi(hd[nt][0], hd[nt][1]);
            *(u32*)&HDH[r1 * 136 + col] = pack_hi(hd[nt][2], hd[nt][3]);
        }
    }

    // ---- split barrier: even warps wrote HD rows 0-15, odd warps rows 16-31;
    //      each half syncs among itself and consumes only its own rows in ph5.
    if (w & 1) { asm volatile("bar.sync 2, 128;" ::: "memory"); }
    else       { asm volatile("bar.sync 1, 128;" ::: "memory"); }

    // ---- phase 5: out = Hd[32,128] @ WoFlat[128,128]  (Hd-hi x Wo-hi) ----
    // Warp handles row block grp = w&1 (16 rows) x 4 n-tiles (gw = w>>1).
    {
        int grp = w & 1, gw = w >> 1;
        float acc[4][4];
#pragma unroll
        for (int ntl = 0; ntl < 4; ntl++)
#pragma unroll
            for (int c = 0; c < 4; c++) acc[ntl][c] = 0.0f;
#pragma unroll
        for (int kt = 0; kt < 8; kt++) {
            u32 ah[4];
            u32 a0 = sb + OFF_XH + ((grp * 16 + lrow) * 136 + kt * 16 + lcol) * 2;
            ldsmA(ah, a0);
#pragma unroll
            for (int ntl = 0; ntl < 4; ntl++) {
                int nt = gw * 4 + ntl;
                uint4 bq = (kt == 0) ? wo_pf[ntl]
                                     : __ldg(g_wo_i + (nt * 8 + kt) * 32 + lane);
                u32 bh[2] = {bq.x, bq.y};
                mma16816(acc[ntl], ah, bh);
            }
        }
        float* ob = out + b * 4096LL;
#pragma unroll
        for (int ntl = 0; ntl < 4; ntl++) {
            int nt = gw * 4 + ntl;
            int r0 = grp * 16 + g, c = nt * 8 + 2 * tig;
            *(float2*)&ob[r0 * 128 + c] = make_float2(acc[ntl][0], acc[ntl][1]);
            *(float2*)&ob[(r0 + 8) * 128 + c] = make_float2(acc[ntl][2], acc[ntl][3]);
        }
    }
}

extern "C" void kernel_launch(void* const* d_in, const int* in_sizes, int n_in,
                              void* d_out, int out_size) {
    const float* x  = (const float*)d_in[0];
    const float* wq = (const float*)d_in[1];
    const float* wk = (const float*)d_in[2];
    const float* wv = (const float*)d_in[3];
    const float* wo = (const float*)d_in[4];
    float* out = (float*)d_out;

    cudaFuncSetAttribute(attn_mma_kernel,
                         cudaFuncAttributeMaxDynamicSharedMemorySize, SMEM_BYTES);

    prep_weights<<<64, 256>>>(wq, wk, wv, wo);
    attn_mma_kernel<<<NB_, 256, SMEM_BYTES>>>(x, out);
}

// round 15
// speedup vs baseline: 1.0635x; 1.0195x over previous
#include <cuda_runtime.h>
#include <cuda_fp16.h>

#define NB_ 16384
#define SCALE_ 0.17677669529663687f  // 1/sqrt(32)

typedef unsigned u32;

// ---- interleaved weight fragment buffers: uint4 = {b0_hi, b1_hi, b0_lo, b1_lo} ----
__device__ __align__(16) uint4 g_wqkv_i[48 * 8 * 32];  // 196608 B
__device__ __align__(16) uint4 g_wo_i[16 * 8 * 32];    //  65536 B

__device__ __forceinline__ void split_pair(float a, float b, u32& hi, u32& lo) {
    __half ha = __float2half_rn(a), hb = __float2half_rn(b);
    __half2 h2 = __halves2half2(ha, hb);
    hi = *(u32*)&h2;
    __half2 l2 = __floats2half2_rn(a - __half2float(ha), b - __half2float(hb));
    lo = *(u32*)&l2;
}
__device__ __forceinline__ u32 pack_hi(float a, float b) {
    __half2 h2 = __floats2half2_rn(a, b);
    return *(u32*)&h2;
}
__device__ __forceinline__ u32 smem_u32(const void* p) {
    u32 a;
    asm("{ .reg .u64 t; cvta.to.shared.u64 t, %1; cvt.u32.u64 %0, t; }" : "=r"(a) : "l"(p));
    return a;
}

__device__ __forceinline__ void mma16816(float* d, const u32* a, const u32* b) {
    asm volatile(
        "mma.sync.aligned.m16n8k16.row.col.f32.f16.f16.f32 "
        "{%0,%1,%2,%3}, {%4,%5,%6,%7}, {%8,%9}, {%0,%1,%2,%3};\n"
        : "+f"(d[0]), "+f"(d[1]), "+f"(d[2]), "+f"(d[3])
        : "r"(a[0]), "r"(a[1]), "r"(a[2]), "r"(a[3]), "r"(b[0]), "r"(b[1]));
}
__device__ __forceinline__ void mma16816_b(float* d, const u32* a, u32 b0, u32 b1) {
    u32 b[2] = {b0, b1};
    mma16816(d, a, b);
}

// ldmatrix x4: four m8n8 b16 tiles in one op.
__device__ __forceinline__ void ldsmA(u32* fr, u32 addr) {
    asm volatile("ldmatrix.sync.aligned.m8n8.x4.shared.b16 {%0,%1,%2,%3}, [%4];"
        : "=r"(fr[0]), "=r"(fr[1]), "=r"(fr[2]), "=r"(fr[3]) : "r"(addr));
}
// ldmatrix x4 transposed (V stored [t][d] -> V^T B-fragments); mapping verified in R13
__device__ __forceinline__ void ldsmT(u32* fr, u32 addr) {
    asm volatile("ldmatrix.sync.aligned.m8n8.x4.trans.shared.b16 {%0,%1,%2,%3}, [%4];"
        : "=r"(fr[0]), "=r"(fr[1]), "=r"(fr[2]), "=r"(fr[3]) : "r"(addr));
}

// ---- prep kernel (verified): 16384 jobs, one uint4 each ----
__global__ void prep_weights(const float* __restrict__ wq, const float* __restrict__ wk,
                             const float* __restrict__ wv, const float* __restrict__ wo) {
    int i = blockIdx.x * blockDim.x + threadIdx.x;
    if (i < 12288) {  // qkv: i = (j*8+kt)*32 + lane
        int lane = i & 31, kt = (i >> 5) & 7, j = i >> 8;
        int tig = lane & 3, gg = lane >> 2;
        int m = j >> 4, h = (j >> 2) & 3, dt = j & 3;
        const float* w = ((m == 0) ? wq : ((m == 1) ? wk : wv)) + h * 4096;
        int d = dt * 8 + gg;
        int e0 = kt * 16 + 2 * tig;
        u32 h0, l0, h1, l1;
        split_pair(w[e0 * 32 + d], w[(e0 + 1) * 32 + d], h0, l0);
        split_pair(w[(e0 + 8) * 32 + d], w[(e0 + 9) * 32 + d], h1, l1);
        g_wqkv_i[i] = make_uint4(h0, h1, l0, l1);
    } else if (i < 16384) {  // wo
        int k = i - 12288;
        int lane = k & 31, kt = (k >> 5) & 7, nt = k >> 8;
        int tig = lane & 3, gg = lane >> 2;
        int o = nt * 8 + gg;
        int hd0 = kt * 16 + 2 * tig;
        u32 h0, l0, h1, l1;
        split_pair(wo[hd0 * 128 + o], wo[(hd0 + 1) * 128 + o], h0, l0);
        split_pair(wo[(hd0 + 8) * 128 + o], wo[(hd0 + 9) * 128 + o], h1, l1);
        g_wo_i[k] = make_uint4(h0, h1, l0, l1);
    }
}

// ---- smem layout (bytes); V stored [t][d] hi-only ----
#define OFF_XH 0
#define OFF_XL 8704
#define OFF_QH 17408
#define OFF_QL 27648
#define OFF_KH 37888
#define OFF_KL 48128
#define OFF_VH 58368
#define SMEM_BYTES 68608

extern __shared__ char smem_raw[];

__global__ __launch_bounds__(256, 2)
void attn_mma_kernel(const float* __restrict__ x, float* __restrict__ out) {
    __half* XH = (__half*)(smem_raw + OFF_XH);
    __half* XL = (__half*)(smem_raw + OFF_XL);
    __half* QH = (__half*)(smem_raw + OFF_QH);
    __half* QL = (__half*)(smem_raw + OFF_QL);
    __half* KH = (__half*)(smem_raw + OFF_KH);
    __half* KL = (__half*)(smem_raw + OFF_KL);
    __half* VH = (__half*)(smem_raw + OFF_VH);
    __half* HDH = XH;  // reuse after phase 1 (fp16-hi only)

    const int tid = threadIdx.x;
    const int lane = tid & 31, w = tid >> 5;
    const int g = lane >> 2, tig = lane & 3;
    const long long b = blockIdx.x;
    const u32 sb = smem_u32(smem_raw);

    // ldmatrix per-lane address offsets
    const int q4 = lane >> 3;
    const int lrow = (lane & 7) + ((q4 & 1) << 3);
    const int lcol = (q4 & 2) << 2;  // 0 or 8 halfs
    // trans-ldmatrix offsets (tile row = t, tile col = d)
    const int vrow = (lane & 7) + ((q4 & 2) << 2);
    const int vcol = (q4 & 1) << 3;

    // ---- prefetch ph1 kt=0 weight fragments (strided j = nj*8 + w) ----
    uint4 wpf[6];
#pragma unroll
    for (int nj = 0; nj < 6; nj++)
        wpf[nj] = __ldg(g_wqkv_i + ((nj * 8 + w) * 8 + 0) * 32 + lane);

    // ---- load x, split fp16 hi/lo ----
    const float2* xb2 = (const float2*)(x + b * 4096LL);
#pragma unroll
    for (int i = 0; i < 8; i++) {
        int idx = tid + i * 256;  // s = idx/64, e2 = idx%64
        int s = idx >> 6, e2 = idx & 63;
        float2 v = xb2[idx];
        u32 hi, lo;
        split_pair(v.x, v.y, hi, lo);
        *(u32*)&XH[s * 136 + e2 * 2] = hi;
        *(u32*)&XL[s * 136 + e2 * 2] = lo;
    }
    __syncthreads();

    // ---- phase 1: QKV = X[32,128] @ Wqkv[128,384] ----
    // j = nj*8 + w; nj 0,1 = Q (3-MMA); 2,3 = K (3-MMA); 4,5 = V (2-MMA).
    {
        float acc[2][6][4];
#pragma unroll
        for (int mt = 0; mt < 2; mt++)
#pragma unroll
            for (int nj = 0; nj < 6; nj++)
#pragma unroll
                for (int c = 0; c < 4; c++) acc[mt][nj][c] = 0.0f;

#pragma unroll
        for (int kt = 0; kt < 8; kt++) {
            u32 ah[2][4], al[2][4];
#pragma unroll
            for (int mt = 0; mt < 2; mt++) {
                u32 a0 = sb + OFF_XH + ((mt * 16 + lrow) * 136 + kt * 16 + lcol) * 2;
                ldsmA(ah[mt], a0);
                ldsmA(al[mt], a0 + (OFF_XL - OFF_XH));
            }
#pragma unroll
            for (int nj = 0; nj < 6; nj++) {
                uint4 bq = (kt == 0) ? wpf[nj]
                                     : __ldg(g_wqkv_i + ((nj * 8 + w) * 8 + kt) * 32 + lane);
                u32 bh[2] = {bq.x, bq.y}, bl[2] = {bq.z, bq.w};
#pragma unroll
                for (int mt = 0; mt < 2; mt++) {
                    mma16816(acc[mt][nj], ah[mt], bh);
                    mma16816(acc[mt][nj], ah[mt], bl);
                    if (nj < 4) mma16816(acc[mt][nj], al[mt], bh);
                }
            }
        }
        // epilogue: split + scatter to Q/K/V
#pragma unroll
        for (int nj = 0; nj < 6; nj++) {
            int j = nj * 8 + w;
            int h = (j >> 2) & 3, dt = j & 3;
#pragma unroll
            for (int mt = 0; mt < 2; mt++) {
                float c0 = acc[mt][nj][0], c1 = acc[mt][nj][1];
                float c2 = acc[mt][nj][2], c3 = acc[mt][nj][3];
                int r0 = mt * 16 + g, r1 = r0 + 8;
                int d0 = dt * 8 + 2 * tig;
                if (nj < 2) {  // Q
                    c0 *= SCALE_; c1 *= SCALE_; c2 *= SCALE_; c3 *= SCALE_;
                    u32 hi, lo;
                    split_pair(c0, c1, hi, lo);
                    *(u32*)&QH[h * 1280 + r0 * 40 + d0] = hi;
                    *(u32*)&QL[h * 1280 + r0 * 40 + d0] = lo;
                    split_pair(c2, c3, hi, lo);
                    *(u32*)&QH[h * 1280 + r1 * 40 + d0] = hi;
                    *(u32*)&QL[h * 1280 + r1 * 40 + d0] = lo;
                } else if (nj < 4) {  // K
                    u32 hi, lo;
                    split_pair(c0, c1, hi, lo);
                    *(u32*)&KH[h * 1280 + r0 * 40 + d0] = hi;
                    *(u32*)&KL[h * 1280 + r0 * 40 + d0] = lo;
                    split_pair(c2, c3, hi, lo);
                    *(u32*)&KH[h * 1280 + r1 * 40 + d0] = hi;
                    *(u32*)&KL[h * 1280 + r1 * 40 + d0] = lo;
                } else {  // V (fp16-hi only), stored [t][d] — clean u32 stores
                    *(u32*)&VH[h * 1280 + r0 * 40 + d0] = pack_hi(c0, c1);
                    *(u32*)&VH[h * 1280 + r1 * 40 + d0] = pack_hi(c2, c3);
                }
            }
        }
    }
    __syncthreads();

    // ---- prefetch ph5 Wo fragments for kt=0,1 (R10 mapping: nt = w*2+ntl) ----
    uint4 wo_pf[4];
#pragma unroll
    for (int i = 0; i < 4; i++) {
        int kt = i >> 1, ntl = i & 1;
        wo_pf[i] = __ldg(g_wo_i + ((w * 2 + ntl) * 8 + kt) * 32 + lane);
    }

    // ---- fused phases 2+3+4 (register-resident, warp-local) ----
    {
        int h = w >> 1, mt = w & 1;
        float acc[4][4];
#pragma unroll
        for (int nt = 0; nt < 4; nt++)
#pragma unroll
            for (int c = 0; c < 4; c++) acc[nt][c] = 0.0f;

        // phase 2: scores = Q @ K^T (3-MMA)
#pragma unroll
        for (int kt = 0; kt < 2; kt++) {
            u32 qh[4], ql[4];
            u32 a0 = sb + OFF_QH + (h * 1280 + (mt * 16 + lrow) * 40 + kt * 16 + lcol) * 2;
            ldsmA(qh, a0);
            ldsmA(ql, a0 + (OFF_QL - OFF_QH));
#pragma unroll
            for (int ntp = 0; ntp < 2; ntp++) {
                u32 kb[4], kl[4];
                u32 ka = sb + OFF_KH + (h * 1280 + (ntp * 16 + lrow) * 40 + kt * 16 + lcol) * 2;
                ldsmA(kb, ka);
                ldsmA(kl, ka + (OFF_KL - OFF_KH));
                mma16816_b(acc[2 * ntp], qh, kb[0], kb[2]);
                mma16816_b(acc[2 * ntp], qh, kl[0], kl[2]);
                mma16816_b(acc[2 * ntp], ql, kb[0], kb[2]);
                mma16816_b(acc[2 * ntp + 1], qh, kb[1], kb[3]);
                mma16816_b(acc[2 * ntp + 1], qh, kl[1], kl[3]);
                mma16816_b(acc[2 * ntp + 1], ql, kb[1], kb[3]);
            }
        }

        // phase 3: softmax in registers (quad shuffle reduction)
        float mx0 = -1e30f, mx1 = -1e30f;
#pragma unroll
        for (int nt = 0; nt < 4; nt++) {
            mx0 = fmaxf(mx0, fmaxf(acc[nt][0], acc[nt][1]));
            mx1 = fmaxf(mx1, fmaxf(acc[nt][2], acc[nt][3]));
        }
        mx0 = fmaxf(mx0, __shfl_xor_sync(0xFFFFFFFF, mx0, 1));
        mx0 = fmaxf(mx0, __shfl_xor_sync(0xFFFFFFFF, mx0, 2));
        mx1 = fmaxf(mx1, __shfl_xor_sync(0xFFFFFFFF, mx1, 1));
        mx1 = fmaxf(mx1, __shfl_xor_sync(0xFFFFFFFF, mx1, 2));
        float s0 = 0.0f, s1 = 0.0f;
#pragma unroll
        for (int nt = 0; nt < 4; nt++) {
            acc[nt][0] = __expf(acc[nt][0] - mx0); s0 += acc[nt][0];
            acc[nt][1] = __expf(acc[nt][1] - mx0); s0 += acc[nt][1];
            acc[nt][2] = __expf(acc[nt][2] - mx1); s1 += acc[nt][2];
            acc[nt][3] = __expf(acc[nt][3] - mx1); s1 += acc[nt][3];
        }
        s0 += __shfl_xor_sync(0xFFFFFFFF, s0, 1);
        s0 += __shfl_xor_sync(0xFFFFFFFF, s0, 2);
        s1 += __shfl_xor_sync(0xFFFFFFFF, s1, 1);
        s1 += __shfl_xor_sync(0xFFFFFFFF, s1, 2);
        float i0 = 1.0f / s0, i1 = 1.0f / s1;

        // normalized scores -> A-fragments, fp16-hi only
        u32 aah[2][4];
#pragma unroll
        for (int kt = 0; kt < 2; kt++) {
            aah[kt][0] = pack_hi(acc[2 * kt][0] * i0,     acc[2 * kt][1] * i0);
            aah[kt][1] = pack_hi(acc[2 * kt][2] * i1,     acc[2 * kt][3] * i1);
            aah[kt][2] = pack_hi(acc[2 * kt + 1][0] * i0, acc[2 * kt + 1][1] * i0);
            aah[kt][3] = pack_hi(acc[2 * kt + 1][2] * i1, acc[2 * kt + 1][3] * i1);
        }

        // phase 4: Hd = A @ V (A-hi x V-hi); V^T fragments via trans-ldmatrix
        float hd[4][4];
#pragma unroll
        for (int nt = 0; nt < 4; nt++)
#pragma unroll
            for (int c = 0; c < 4; c++) hd[nt][c] = 0.0f;
#pragma unroll
        for (int kt = 0; kt < 2; kt++) {
#pragma unroll
            for (int ntp = 0; ntp < 2; ntp++) {
                u32 vb[4];
                u32 va = sb + OFF_VH + (h * 1280 + (kt * 16 + vrow) * 40 + ntp * 16 + vcol) * 2;
                ldsmT(vb, va);
                mma16816_b(hd[2 * ntp], aah[kt], vb[0], vb[2]);
                mma16816_b(hd[2 * ntp + 1], aah[kt], vb[1], vb[3]);
            }
        }
        // epilogue -> HDH only (fp16-hi)
#pragma unroll
        for (int nt = 0; nt < 4; nt++) {
            int col = h * 32 + nt * 8 + 2 * tig;
            int r0 = mt * 16 + g, r1 = r0 + 8;
            *(u32*)&HDH[r0 * 136 + col] = pack_hi(hd[nt][0], hd[nt][1]);
            *(u32*)&HDH[r1 * 136 + col] = pack_hi(hd[nt][2], hd[nt][3]);
        }
    }
    __syncthreads();

    // ---- phase 5: out = Hd[32,128] @ WoFlat[128,128]  (Hd-hi x Wo-hi; R10 mapping) ----
    {
        float acc[2][2][4];
#pragma unroll
        for (int mt = 0; mt < 2; mt++)
#pragma unroll
            for (int n = 0; n < 2; n++)
#pragma unroll
                for (int c = 0; c < 4; c++) acc[mt][n][c] = 0.0f;
#pragma unroll
        for (int kt = 0; kt < 8; kt++) {
            u32 ah[2][4];
#pragma unroll
            for (int mt = 0; mt < 2; mt++) {
                u32 a0 = sb + OFF_XH + ((mt * 16 + lrow) * 136 + kt * 16 + lcol) * 2;
                ldsmA(ah[mt], a0);
            }
#pragma unroll
            for (int ntl = 0; ntl < 2; ntl++) {
                int nt = w * 2 + ntl;
                uint4 bq = (kt < 2) ? wo_pf[kt * 2 + ntl]
                                    : __ldg(g_wo_i + (nt * 8 + kt) * 32 + lane);
                u32 bh[2] = {bq.x, bq.y};
#pragma unroll
                for (int mt = 0; mt < 2; mt++)
                    mma16816(acc[mt][ntl], ah[mt], bh);
            }
        }
        float* ob = out + b * 4096LL;
#pragma unroll
        for (int mt = 0; mt < 2; mt++)
#pragma unroll
            for (int ntl = 0; ntl < 2; ntl++) {
                int nt = w * 2 + ntl;
                int r0 = mt * 16 + g, c = nt * 8 + 2 * tig;
                *(float2*)&ob[r0 * 128 + c] = make_float2(acc[mt][ntl][0], acc[mt][ntl][1]);
                *(float2*)&ob[(r0 + 8) * 128 + c] = make_float2(acc[mt][ntl][2], acc[mt][ntl][3]);
            }
    }
}

extern "C" void kernel_launch(void* const* d_in, const int* in_sizes, int n_in,
                              void* d_out, int out_size) {
    const float* x  = (const float*)d_in[0];
    const float* wq = (const float*)d_in[1];
    const float* wk = (const float*)d_in[2];
    const float* wv = (const float*)d_in[3];
    const float* wo = (const float*)d_in[4];
    float* out = (float*)d_out;

    cudaFuncSetAttribute(attn_mma_kernel,
                         cudaFuncAttributeMaxDynamicSharedMemorySize, SMEM_BYTES);

    prep_weights<<<64, 256>>>(wq, wk, wv, wo);
    attn_mma_kernel<<<NB_, 256, SMEM_BYTES>>>(x, out);
}

// round 16
// speedup vs baseline: 1.0808x; 1.0162x over previous
#include <cuda_runtime.h>
#include <cuda_fp16.h>

#define NB_ 16384
#define SCALE_ 0.17677669529663687f  // 1/sqrt(32)

typedef unsigned u32;

// ---- interleaved weight fragment buffers: uint4 = {b0_hi, b1_hi, b0_lo, b1_lo} ----
__device__ __align__(16) uint4 g_wqkv_i[48 * 8 * 32];  // 196608 B
__device__ __align__(16) uint4 g_wo_i[16 * 8 * 32];    //  65536 B

__device__ __forceinline__ void split_pair(float a, float b, u32& hi, u32& lo) {
    __half ha = __float2half_rn(a), hb = __float2half_rn(b);
    __half2 h2 = __halves2half2(ha, hb);
    hi = *(u32*)&h2;
    __half2 l2 = __floats2half2_rn(a - __half2float(ha), b - __half2float(hb));
    lo = *(u32*)&l2;
}
__device__ __forceinline__ u32 pack_hi(float a, float b) {
    __half2 h2 = __floats2half2_rn(a, b);
    return *(u32*)&h2;
}
__device__ __forceinline__ void split_one(float v, __half* ph, __half* pl) {
    __half h = __float2half_rn(v);
    *ph = h;
    *pl = __float2half_rn(v - __half2float(h));
}
__device__ __forceinline__ u32 smem_u32(const void* p) {
    u32 a;
    asm("{ .reg .u64 t; cvta.to.shared.u64 t, %1; cvt.u32.u64 %0, t; }" : "=r"(a) : "l"(p));
    return a;
}

__device__ __forceinline__ void mma16816(float* d, const u32* a, const u32* b) {
    asm volatile(
        "mma.sync.aligned.m16n8k16.row.col.f32.f16.f16.f32 "
        "{%0,%1,%2,%3}, {%4,%5,%6,%7}, {%8,%9}, {%0,%1,%2,%3};\n"
        : "+f"(d[0]), "+f"(d[1]), "+f"(d[2]), "+f"(d[3])
        : "r"(a[0]), "r"(a[1]), "r"(a[2]), "r"(a[3]), "r"(b[0]), "r"(b[1]));
}
__device__ __forceinline__ void mma16816_b(float* d, const u32* a, u32 b0, u32 b1) {
    u32 b[2] = {b0, b1};
    mma16816(d, a, b);
}

// ldmatrix x4: four m8n8 b16 tiles in one op.
__device__ __forceinline__ void ldsmA(u32* fr, u32 addr) {
    asm volatile("ldmatrix.sync.aligned.m8n8.x4.shared.b16 {%0,%1,%2,%3}, [%4];"
        : "=r"(fr[0]), "=r"(fr[1]), "=r"(fr[2]), "=r"(fr[3]) : "r"(addr));
}

// ---- prep kernel (verified): 16384 jobs, one uint4 each ----
__global__ void prep_weights(const float* __restrict__ wq, const float* __restrict__ wk,
                             const float* __restrict__ wv, const float* __restrict__ wo) {
    int i = blockIdx.x * blockDim.x + threadIdx.x;
    if (i < 12288) {  // qkv: i = (j*8+kt)*32 + lane
        int lane = i & 31, kt = (i >> 5) & 7, j = i >> 8;
        int tig = lane & 3, gg = lane >> 2;
        int m = j >> 4, h = (j >> 2) & 3, dt = j & 3;
        const float* w = ((m == 0) ? wq : ((m == 1) ? wk : wv)) + h * 4096;
        int d = dt * 8 + gg;
        int e0 = kt * 16 + 2 * tig;
        u32 h0, l0, h1, l1;
        split_pair(w[e0 * 32 + d], w[(e0 + 1) * 32 + d], h0, l0);
        split_pair(w[(e0 + 8) * 32 + d], w[(e0 + 9) * 32 + d], h1, l1);
        g_wqkv_i[i] = make_uint4(h0, h1, l0, l1);
    } else if (i < 16384) {  // wo
        int k = i - 12288;
        int lane = k & 31, kt = (k >> 5) & 7, nt = k >> 8;
        int tig = lane & 3, gg = lane >> 2;
        int o = nt * 8 + gg;
        int hd0 = kt * 16 + 2 * tig;
        u32 h0, l0, h1, l1;
        split_pair(wo[hd0 * 128 + o], wo[(hd0 + 1) * 128 + o], h0, l0);
        split_pair(wo[(hd0 + 8) * 128 + o], wo[(hd0 + 9) * 128 + o], h1, l1);
        g_wo_i[k] = make_uint4(h0, h1, l0, l1);
    }
}

// ---- R10 smem layout (bytes) ----
#define OFF_XH 0
#define OFF_XL 8704
#define OFF_QH 17408
#define OFF_QL 27648
#define OFF_KH 37888
#define OFF_KL 48128
#define OFF_VTH 58368
#define SMEM_BYTES 68608

extern __shared__ char smem_raw[];

__global__ __launch_bounds__(256, 2)
void attn_mma_kernel(const float* __restrict__ x, float* __restrict__ out) {
    __half* XH = (__half*)(smem_raw + OFF_XH);
    __half* XL = (__half*)(smem_raw + OFF_XL);
    __half* QH = (__half*)(smem_raw + OFF_QH);
    __half* QL = (__half*)(smem_raw + OFF_QL);
    __half* KH = (__half*)(smem_raw + OFF_KH);
    __half* KL = (__half*)(smem_raw + OFF_KL);
    __half* VTH = (__half*)(smem_raw + OFF_VTH);
    __half* HDH = XH;  // reuse after phase 1 (fp16-hi only)

    const int tid = threadIdx.x;
    const int lane = tid & 31, w = tid >> 5;
    const int g = lane >> 2, tig = lane & 3;
    const long long b = blockIdx.x;
    const u32 sb = smem_u32(smem_raw);

    // ldmatrix per-lane address offsets
    const int q4 = lane >> 3;
    const int lrow = (lane & 7) + ((q4 & 1) << 3);
    const int lcol = (q4 & 2) << 2;  // 0 or 8 halfs

    // ---- prefetch ph1 kt=0 weight fragments (overlaps x DRAM latency) ----
    uint4 wpf[6];
#pragma unroll
    for (int nj = 0; nj < 6; nj++)
        wpf[nj] = __ldg(g_wqkv_i + ((nj * 8 + w) * 8 + 0) * 32 + lane);

    // ---- load x, split fp16 hi/lo ----
    const float2* xb2 = (const float2*)(x + b * 4096LL);
#pragma unroll
    for (int i = 0; i < 8; i++) {
        int idx = tid + i * 256;  // s = idx/64, e2 = idx%64
        int s = idx >> 6, e2 = idx & 63;
        float2 v = xb2[idx];
        u32 hi, lo;
        split_pair(v.x, v.y, hi, lo);
        *(u32*)&XH[s * 136 + e2 * 2] = hi;
        *(u32*)&XL[s * 136 + e2 * 2] = lo;
    }
    __syncthreads();

    uint4 wo_pf[4];  // declared here; issued right after ph1 mainloop

    // ---- phase 1: QKV = X[32,128] @ Wqkv[128,384] ----
    // j = nj*8 + w; nj 0,1 = Q (3-MMA); 2,3 = K (3-MMA); 4,5 = V (2-MMA).
    {
        float acc[2][6][4];
#pragma unroll
        for (int mt = 0; mt < 2; mt++)
#pragma unroll
            for (int nj = 0; nj < 6; nj++)
#pragma unroll
                for (int c = 0; c < 4; c++) acc[mt][nj][c] = 0.0f;

#pragma unroll
        for (int kt = 0; kt < 8; kt++) {
            u32 ah[2][4], al[2][4];
#pragma unroll
            for (int mt = 0; mt < 2; mt++) {
                u32 a0 = sb + OFF_XH + ((mt * 16 + lrow) * 136 + kt * 16 + lcol) * 2;
                ldsmA(ah[mt], a0);
                ldsmA(al[mt], a0 + (OFF_XL - OFF_XH));
            }
#pragma unroll
            for (int nj = 0; nj < 6; nj++) {
                uint4 bq = (kt == 0) ? wpf[nj]
                                     : __ldg(g_wqkv_i + ((nj * 8 + w) * 8 + kt) * 32 + lane);
                u32 bh[2] = {bq.x, bq.y}, bl[2] = {bq.z, bq.w};
#pragma unroll
                for (int mt = 0; mt < 2; mt++) {
                    mma16816(acc[mt][nj], ah[mt], bh);
                    mma16816(acc[mt][nj], ah[mt], bl);
                    if (nj < 4) mma16816(acc[mt][nj], al[mt], bh);
                }
            }
        }

        // ---- issue ph5 Wo prefetch EARLY: covered by epilogue + S2 barrier ----
#pragma unroll
        for (int i = 0; i < 4; i++) {
            int kt = i >> 1, ntl = i & 1;
            wo_pf[i] = __ldg(g_wo_i + ((w * 2 + ntl) * 8 + kt) * 32 + lane);
        }

        // epilogue: split + scatter to Q/K/VT
#pragma unroll
        for (int nj = 0; nj < 6; nj++) {
            int j = nj * 8 + w;
            int h = (j >> 2) & 3, dt = j & 3;
#pragma unroll
            for (int mt = 0; mt < 2; mt++) {
                float c0 = acc[mt][nj][0], c1 = acc[mt][nj][1];
                float c2 = acc[mt][nj][2], c3 = acc[mt][nj][3];
                int r0 = mt * 16 + g, r1 = r0 + 8;
                int d0 = dt * 8 + 2 * tig;
                if (nj < 2) {  // Q
                    c0 *= SCALE_; c1 *= SCALE_; c2 *= SCALE_; c3 *= SCALE_;
                    u32 hi, lo;
                    split_pair(c0, c1, hi, lo);
                    *(u32*)&QH[h * 1280 + r0 * 40 + d0] = hi;
                    *(u32*)&QL[h * 1280 + r0 * 40 + d0] = lo;
                    split_pair(c2, c3, hi, lo);
                    *(u32*)&QH[h * 1280 + r1 * 40 + d0] = hi;
                    *(u32*)&QL[h * 1280 + r1 * 40 + d0] = lo;
                } else if (nj < 4) {  // K
                    u32 hi, lo;
                    split_pair(c0, c1, hi, lo);
                    *(u32*)&KH[h * 1280 + r0 * 40 + d0] = hi;
                    *(u32*)&KL[h * 1280 + r0 * 40 + d0] = lo;
                    split_pair(c2, c3, hi, lo);
                    *(u32*)&KH[h * 1280 + r1 * 40 + d0] = hi;
                    *(u32*)&KL[h * 1280 + r1 * 40 + d0] = lo;
                } else {  // V (fp16-hi only), transposed: VT[h][d][t]
                    VTH[h * 1280 + d0 * 40 + r0]       = __float2half_rn(c0);
                    VTH[h * 1280 + (d0 + 1) * 40 + r0] = __float2half_rn(c1);
                    VTH[h * 1280 + d0 * 40 + r1]       = __float2half_rn(c2);
                    VTH[h * 1280 + (d0 + 1) * 40 + r1] = __float2half_rn(c3);
                }
            }
        }
    }
    __syncthreads();

    // ---- fused phases 2+3+4 (register-resident, warp-local) ----
    {
        int h = w >> 1, mt = w & 1;
        float acc[4][4];
#pragma unroll
        for (int nt = 0; nt < 4; nt++)
#pragma unroll
            for (int c = 0; c < 4; c++) acc[nt][c] = 0.0f;

        // phase 2: scores = Q @ K^T (3-MMA)
#pragma unroll
        for (int kt = 0; kt < 2; kt++) {
            u32 qh[4], ql[4];
            u32 a0 = sb + OFF_QH + (h * 1280 + (mt * 16 + lrow) * 40 + kt * 16 + lcol) * 2;
            ldsmA(qh, a0);
            ldsmA(ql, a0 + (OFF_QL - OFF_QH));
#pragma unroll
            for (int ntp = 0; ntp < 2; ntp++) {
                u32 kb[4], kl[4];
                u32 ka = sb + OFF_KH + (h * 1280 + (ntp * 16 + lrow) * 40 + kt * 16 + lcol) * 2;
                ldsmA(kb, ka);
                ldsmA(kl, ka + (OFF_KL - OFF_KH));
                mma16816_b(acc[2 * ntp], qh, kb[0], kb[2]);
                mma16816_b(acc[2 * ntp], qh, kl[0], kl[2]);
                mma16816_b(acc[2 * ntp], ql, kb[0], kb[2]);
                mma16816_b(acc[2 * ntp + 1], qh, kb[1], kb[3]);
                mma16816_b(acc[2 * ntp + 1], qh, kl[1], kl[3]);
                mma16816_b(acc[2 * ntp + 1], ql, kb[1], kb[3]);
            }
        }

        // phase 3: softmax in registers (quad shuffle reduction)
        float mx0 = -1e30f, mx1 = -1e30f;
#pragma unroll
        for (int nt = 0; nt < 4; nt++) {
            mx0 = fmaxf(mx0, fmaxf(acc[nt][0], acc[nt][1]));
            mx1 = fmaxf(mx1, fmaxf(acc[nt][2], acc[nt][3]));
        }
        mx0 = fmaxf(mx0, __shfl_xor_sync(0xFFFFFFFF, mx0, 1));
        mx0 = fmaxf(mx0, __shfl_xor_sync(0xFFFFFFFF, mx0, 2));
        mx1 = fmaxf(mx1, __shfl_xor_sync(0xFFFFFFFF, mx1, 1));
        mx1 = fmaxf(mx1, __shfl_xor_sync(0xFFFFFFFF, mx1, 2));
        float s0 = 0.0f, s1 = 0.0f;
#pragma unroll
        for (int nt = 0; nt < 4; nt++) {
            acc[nt][0] = __expf(acc[nt][0] - mx0); s0 += acc[nt][0];
            acc[nt][1] = __expf(acc[nt][1] - mx0); s0 += acc[nt][1];
            acc[nt][2] = __expf(acc[nt][2] - mx1); s1 += acc[nt][2];
            acc[nt][3] = __expf(acc[nt][3] - mx1); s1 += acc[nt][3];
        }
        s0 += __shfl_xor_sync(0xFFFFFFFF, s0, 1);
        s0 += __shfl_xor_sync(0xFFFFFFFF, s0, 2);
        s1 += __shfl_xor_sync(0xFFFFFFFF, s1, 1);
        s1 += __shfl_xor_sync(0xFFFFFFFF, s1, 2);
        float i0 = 1.0f / s0, i1 = 1.0f / s1;

        // normalized scores -> A-fragments, fp16-hi only
        u32 aah[2][4];
#pragma unroll
        for (int kt = 0; kt < 2; kt++) {
            aah[kt][0] = pack_hi(acc[2 * kt][0] * i0,     acc[2 * kt][1] * i0);
            aah[kt][1] = pack_hi(acc[2 * kt][2] * i1,     acc[2 * kt][3] * i1);
            aah[kt][2] = pack_hi(acc[2 * kt + 1][0] * i0, acc[2 * kt + 1][1] * i0);
            aah[kt][3] = pack_hi(acc[2 * kt + 1][2] * i1, acc[2 * kt + 1][3] * i1);
        }

        // phase 4: Hd = A @ V (A-hi x V-hi); VT B-fragments via straight ldmatrix
        float hd[4][4];
#pragma unroll
        for (int nt = 0; nt < 4; nt++)
#pragma unroll
            for (int c = 0; c < 4; c++) hd[nt][c] = 0.0f;
#pragma unroll
        for (int kt = 0; kt < 2; kt++) {
#pragma unroll
            for (int ntp = 0; ntp < 2; ntp++) {
                u32 vb[4];
                u32 va = sb + OFF_VTH + (h * 1280 + (ntp * 16 + lrow) * 40 + kt * 16 + lcol) * 2;
                ldsmA(vb, va);
                mma16816_b(hd[2 * ntp], aah[kt], vb[0], vb[2]);
                mma16816_b(hd[2 * ntp + 1], aah[kt], vb[1], vb[3]);
            }
        }
        // epilogue -> HDH only (fp16-hi)
#pragma unroll
        for (int nt = 0; nt < 4; nt++) {
            int col = h * 32 + nt * 8 + 2 * tig;
            int r0 = mt * 16 + g, r1 = r0 + 8;
            *(u32*)&HDH[r0 * 136 + col] = pack_hi(hd[nt][0], hd[nt][1]);
            *(u32*)&HDH[r1 * 136 + col] = pack_hi(hd[nt][2], hd[nt][3]);
        }
    }
    __syncthreads();

    // ---- phase 5: out = Hd[32,128] @ WoFlat[128,128]  (Hd-hi x Wo-hi) ----
    {
        float acc[2][2][4];
#pragma unroll
        for (int mt = 0; mt < 2; mt++)
#pragma unroll
            for (int n = 0; n < 2; n++)
#pragma unroll
                for (int c = 0; c < 4; c++) acc[mt][n][c] = 0.0f;
#pragma unroll
        for (int kt = 0; kt < 8; kt++) {
            u32 ah[2][4];
#pragma unroll
            for (int mt = 0; mt < 2; mt++) {
                u32 a0 = sb + OFF_XH + ((mt * 16 + lrow) * 136 + kt * 16 + lcol) * 2;
                ldsmA(ah[mt], a0);
            }
#pragma unroll
            for (int ntl = 0; ntl < 2; ntl++) {
                int nt = w * 2 + ntl;
                uint4 bq = (kt < 2) ? wo_pf[kt * 2 + ntl]
                                    : __ldg(g_wo_i + (nt * 8 + kt) * 32 + lane);
                u32 bh[2] = {bq.x, bq.y};
#pragma unroll
                for (int mt = 0; mt < 2; mt++)
                    mma16816(acc[mt][ntl], ah[mt], bh);
            }
        }
        float* ob = out + b * 4096LL;
#pragma unroll
        for (int mt = 0; mt < 2; mt++)
#pragma unroll
            for (int ntl = 0; ntl < 2; ntl++) {
                int nt = w * 2 + ntl;
                int r0 = mt * 16 + g, c = nt * 8 + 2 * tig;
                *(float2*)&ob[r0 * 128 + c] = make_float2(acc[mt][ntl][0], acc[mt][ntl][1]);
                *(float2*)&ob[(r0 + 8) * 128 + c] = make_float2(acc[mt][ntl][2], acc[mt][ntl][3]);
            }
    }
}

extern "C" void kernel_launch(void* const* d_in, const int* in_sizes, int n_in,
                              void* d_out, int out_size) {
    const float* x  = (const float*)d_in[0];
    const float* wq = (const float*)d_in[1];
    const float* wk = (const float*)d_in[2];
    const float* wv = (const float*)d_in[3];
    const float* wo = (const float*)d_in[4];
    float* out = (float*)d_out;

    cudaFuncSetAttribute(attn_mma_kernel,
                         cudaFuncAttributeMaxDynamicSharedMemorySize, SMEM_BYTES);

    prep_weights<<<64, 256>>>(wq, wk, wv, wo);
    attn_mma_kernel<<<NB_, 256, SMEM_BYTES>>>(x, out);
}